// round 1
// baseline (speedup 1.0000x reference)
#include <cuda_runtime.h>
#include <cuda_bf16.h>
#include <math.h>

// Problem constants
#define NN   16384
#define BB   256
#define NPG  64
#define DEG  8
#define EE   (NN*DEG)      // 131072
#define HH   256
#define FN   133
#define FE   14

// ---------------- scratch (device globals; no runtime allocation) ------------
__device__ float g_in [NN*HH];       // i_n
__device__ float g_ie [EE*HH];       // i_e
__device__ float g_he [EE*HH];       // h_e
__device__ float g_hn [NN*HH];       // h_n
__device__ float g_tmp[NN*HH];       // h_n @ Wm (also reused for h_n after Wlr)
__device__ float g_cat[NN*3*HH];     // concat(m_final, h_n, i_n)
__device__ float g_msg[NN*HH];
__device__ float g_xgf[NN*3*HH];
__device__ float g_xgb[NN*3*HH];
__device__ float g_hf [BB*HH];
__device__ float g_hb [BB*HH];
__device__ float g_ghf[BB*3*HH];
__device__ float g_ghb[BB*3*HH];
__device__ float g_accf[BB*HH];
__device__ float g_accb[BB*HH];

__device__ __forceinline__ float sigmoidf_(float x){ return 1.0f/(1.0f+expf(-x)); }

// ---------------- generic fp32 tiled GEMM: C = op(A@W + bias) ----------------
template<int BM,int BN,int BK,int TM,int TN,bool RELU>
__global__ __launch_bounds__((BM/TM)*(BN/TN))
void sgemm(int M,int N,int K,
           const float* __restrict__ A,
           const float* __restrict__ W,
           const float* __restrict__ bias,
           float* __restrict__ C)
{
    constexpr int TX = BN/TN, TY = BM/TM, THREADS = TX*TY;
    __shared__ float As[BK][BM+4];
    __shared__ float Ws[BK][BN];
    const int tid = threadIdx.x;
    const int tx  = tid % TX, ty = tid / TX;
    const int row0 = blockIdx.y*BM, col0 = blockIdx.x*BN;

    float acc[TM][TN];
    #pragma unroll
    for (int i=0;i<TM;i++)
        #pragma unroll
        for (int j=0;j<TN;j++) acc[i][j]=0.f;

    for (int k0 = 0; k0 < K; k0 += BK){
        #pragma unroll 4
        for (int i = tid; i < BM*BK; i += THREADS){
            int kk = i % BK, m = i / BK;
            int gr = row0 + m, gk = k0 + kk;
            As[kk][m] = (gr < M && gk < K) ? A[(size_t)gr*K + gk] : 0.f;
        }
        #pragma unroll 4
        for (int i = tid; i < BK*BN; i += THREADS){
            int n = i % BN, kk = i / BN;
            int gk = k0 + kk, gc = col0 + n;
            Ws[kk][n] = (gk < K && gc < N) ? W[(size_t)gk*N + gc] : 0.f;
        }
        __syncthreads();
        #pragma unroll
        for (int k = 0; k < BK; k++){
            float a[TM], b[TN];
            #pragma unroll
            for (int i=0;i<TM;i++) a[i] = As[k][ty*TM+i];
            #pragma unroll
            for (int j=0;j<TN;j++) b[j] = Ws[k][tx*TN+j];
            #pragma unroll
            for (int i=0;i<TM;i++)
                #pragma unroll
                for (int j=0;j<TN;j++)
                    acc[i][j] += a[i]*b[j];
        }
        __syncthreads();
    }
    #pragma unroll
    for (int i=0;i<TM;i++){
        int gr = row0 + ty*TM + i;
        if (gr >= M) continue;
        #pragma unroll
        for (int j=0;j<TN;j++){
            int gc = col0 + tx*TN + j;
            if (gc >= N) continue;
            float v = acc[i][j] + bias[gc];
            if (RELU) v = fmaxf(v, 0.f);
            C[(size_t)gr*N + gc] = v;
        }
    }
}

// ------------- node aggregate: h_n_out = h_n_in + segsum*segmax ---------------
__global__ void aggregate_k(const float* __restrict__ he,
                            const float* __restrict__ hn_in,
                            float* __restrict__ hn_out)
{
    int i = blockIdx.x, j = threadIdx.x;
    const float* base = he + (size_t)i*DEG*HH + j;
    float s = 0.f, m = -INFINITY;
    #pragma unroll
    for (int d=0; d<DEG; d++){ float v = base[(size_t)d*HH]; s += v; m = fmaxf(m, v); }
    hn_out[(size_t)i*HH + j] = hn_in[(size_t)i*HH + j] + s*m;
}

// ------------- edge update: h_e = relu(i_e + tmp[src]) -----------------------
__global__ void edge_update_k(const float* __restrict__ ie,
                              const float* __restrict__ tmp,
                              const int* __restrict__ src,
                              float* __restrict__ he)
{
    int e = blockIdx.x, j = threadIdx.x;
    int s = __ldg(&src[e]);
    float v = ie[(size_t)e*HH + j] + tmp[(size_t)s*HH + j];
    he[(size_t)e*HH + j] = fmaxf(v, 0.f);
}

// ------------- build concat( m_final, h_n, i_n ) ------------------------------
__global__ void build_cat_k(const float* __restrict__ he,
                            const float* __restrict__ hn,
                            const float* __restrict__ in_,
                            float* __restrict__ cat)
{
    int i = blockIdx.x, j = threadIdx.x;
    const float* base = he + (size_t)i*DEG*HH + j;
    float s = 0.f, m = -INFINITY;
    #pragma unroll
    for (int d=0; d<DEG; d++){ float v = base[(size_t)d*HH]; s += v; m = fmaxf(m, v); }
    size_t r = (size_t)i*3*HH;
    cat[r + j]        = s*m;
    cat[r + HH + j]   = hn[(size_t)i*HH + j];
    cat[r + 2*HH + j] = in_[(size_t)i*HH + j];
}

// ------------- msg = relu(h_n + gbias) ----------------------------------------
__global__ void msg_k(const float* __restrict__ hnl,
                      const float* __restrict__ gbias,
                      float* __restrict__ msg)
{
    int i = blockIdx.x, j = threadIdx.x;
    msg[(size_t)i*HH + j] = fmaxf(hnl[(size_t)i*HH + j] + gbias[j], 0.f);
}

// ------------- h0 = per-graph max; init accumulators -------------------------
__global__ void init_h0_k(const float* __restrict__ hnl,
                          float* __restrict__ hf, float* __restrict__ hb,
                          float* __restrict__ accf, float* __restrict__ accb)
{
    int b = blockIdx.x, j = threadIdx.x;
    float m = -INFINITY;
    #pragma unroll 8
    for (int t=0; t<NPG; t++)
        m = fmaxf(m, hnl[((size_t)b*NPG + t)*HH + j]);
    hf[b*HH+j] = m; hb[b*HH+j] = m;
    accf[b*HH+j] = 0.f; accb[b*HH+j] = 0.f;
}

// ------------- GRU recurrent GEMM (both directions): gh = h@Wh + bh ----------
// M=256 (graphs), N=768 (3H), K=256. 64x64 tiles, blockIdx.z = direction.
__global__ __launch_bounds__(256) void gru_gh_k(
    const float* __restrict__ hf, const float* __restrict__ hb,
    const float* __restrict__ Whf, const float* __restrict__ Whb,
    const float* __restrict__ bhf, const float* __restrict__ bhb,
    float* __restrict__ ghf, float* __restrict__ ghb)
{
    const float* A    = blockIdx.z ? hb  : hf;
    const float* W    = blockIdx.z ? Whb : Whf;
    const float* bias = blockIdx.z ? bhb : bhf;
    float*       C    = blockIdx.z ? ghb : ghf;

    __shared__ float As[16][68];
    __shared__ float Ws[16][64];
    int tid = threadIdx.x, tx = tid % 16, ty = tid / 16;
    int row0 = blockIdx.y*64, col0 = blockIdx.x*64;
    float acc[4][4];
    #pragma unroll
    for(int i=0;i<4;i++)
        #pragma unroll
        for(int j=0;j<4;j++) acc[i][j]=0.f;

    for (int k0 = 0; k0 < HH; k0 += 16){
        #pragma unroll
        for (int i = tid; i < 64*16; i += 256){
            int kk = i % 16, m = i / 16;
            As[kk][m] = A[(row0+m)*HH + k0 + kk];
        }
        #pragma unroll
        for (int i = tid; i < 16*64; i += 256){
            int n = i % 64, kk = i / 64;
            Ws[kk][n] = W[(k0+kk)*(3*HH) + col0 + n];
        }
        __syncthreads();
        #pragma unroll
        for (int k=0;k<16;k++){
            float a[4], b[4];
            #pragma unroll
            for(int i=0;i<4;i++) a[i] = As[k][ty*4+i];
            #pragma unroll
            for(int j=0;j<4;j++) b[j] = Ws[k][tx*4+j];
            #pragma unroll
            for(int i=0;i<4;i++)
                #pragma unroll
                for(int j=0;j<4;j++) acc[i][j] += a[i]*b[j];
        }
        __syncthreads();
    }
    #pragma unroll
    for(int i=0;i<4;i++){
        int gr = row0 + ty*4 + i;
        #pragma unroll
        for(int j=0;j<4;j++){
            int gc = col0 + tx*4 + j;
            C[(size_t)gr*(3*HH) + gc] = acc[i][j] + bias[gc];
        }
    }
}

// ------------- GRU gates (both directions), in-place h, accumulate mean ------
__global__ void gru_gate_k(const float* __restrict__ xgf, const float* __restrict__ xgb,
                           const float* __restrict__ ghf, const float* __restrict__ ghb,
                           float* __restrict__ hf, float* __restrict__ hb,
                           float* __restrict__ accf, float* __restrict__ accb,
                           int step)
{
    int dir = blockIdx.y;
    int b = blockIdx.x, j = threadIdx.x;
    const float* xg  = dir ? xgb : xgf;
    const float* gh  = dir ? ghb : ghf;
    float* h   = dir ? hb  : hf;
    float* acc = dir ? accb : accf;
    int t = dir ? (NPG-1-step) : step;

    const float* x = xg + ((size_t)b*NPG + t)*(3*HH);
    const float* g = gh + (size_t)b*(3*HH);
    float r = sigmoidf_(x[j]        + g[j]);
    float z = sigmoidf_(x[HH + j]   + g[HH + j]);
    float n = tanhf    (x[2*HH + j] + r*g[2*HH + j]);
    float hv = h[b*HH + j];
    float hn = (1.0f - z)*n + z*hv;
    h[b*HH + j]   = hn;
    acc[b*HH + j] += hn;
}

// ------------- readout: out = relu(g@W1+b1)@W2 + b2 --------------------------
__global__ void readout_k(const float* __restrict__ accf, const float* __restrict__ accb,
                          const float* __restrict__ W1, const float* __restrict__ b1,
                          const float* __restrict__ W2, const float* __restrict__ b2,
                          float* __restrict__ out)
{
    int b = blockIdx.x, j = threadIdx.x; // 256 threads
    __shared__ float gsh[2*HH];
    __shared__ float red[HH];
    gsh[j]      = accf[b*HH + j] * (1.0f/NPG);
    gsh[HH + j] = accb[b*HH + j] * (1.0f/NPG);
    __syncthreads();
    float y = b1[j];
    #pragma unroll 8
    for (int k=0; k<2*HH; k++)
        y += gsh[k] * W1[k*HH + j];
    y = fmaxf(y, 0.f);
    red[j] = y * W2[j];
    __syncthreads();
    for (int s=128; s>0; s>>=1){
        if (j < s) red[j] += red[j+s];
        __syncthreads();
    }
    if (j == 0) out[b] = red[0] + b2[0];
}

// =============================================================================
extern "C" void kernel_launch(void* const* d_in, const int* in_sizes, int n_in,
                              void* d_out, int out_size)
{
    const float* node_x = (const float*)d_in[0];
    const float* edge_x = (const float*)d_in[1];
    const int*   src    = (const int*)  d_in[2];
    // d_in[3] = dst (structure known: repeat(arange(N), DEG)) — unused
    const float* Wn  = (const float*)d_in[4];  const float* bn  = (const float*)d_in[5];
    const float* We  = (const float*)d_in[6];  const float* be  = (const float*)d_in[7];
    const float* Wm0 = (const float*)d_in[8];  const float* bm0 = (const float*)d_in[9];
    const float* Wm1 = (const float*)d_in[10]; const float* bm1 = (const float*)d_in[11];
    const float* Wlr = (const float*)d_in[12]; const float* blr = (const float*)d_in[13];
    const float* gbias = (const float*)d_in[14];
    const float* Wif = (const float*)d_in[15]; const float* Whf = (const float*)d_in[16];
    const float* bif = (const float*)d_in[17]; const float* bhf = (const float*)d_in[18];
    const float* Wib = (const float*)d_in[19]; const float* Whb = (const float*)d_in[20];
    const float* bib = (const float*)d_in[21]; const float* bhb = (const float*)d_in[22];
    const float* W1  = (const float*)d_in[23]; const float* b1  = (const float*)d_in[24];
    const float* W2  = (const float*)d_in[25]; const float* b2  = (const float*)d_in[26];
    float* out = (float*)d_out;

    float *p_in, *p_ie, *p_he, *p_hn, *p_tmp, *p_cat, *p_msg, *p_xgf, *p_xgb;
    float *p_hf, *p_hb, *p_ghf, *p_ghb, *p_accf, *p_accb;
    cudaGetSymbolAddress((void**)&p_in,  g_in);
    cudaGetSymbolAddress((void**)&p_ie,  g_ie);
    cudaGetSymbolAddress((void**)&p_he,  g_he);
    cudaGetSymbolAddress((void**)&p_hn,  g_hn);
    cudaGetSymbolAddress((void**)&p_tmp, g_tmp);
    cudaGetSymbolAddress((void**)&p_cat, g_cat);
    cudaGetSymbolAddress((void**)&p_msg, g_msg);
    cudaGetSymbolAddress((void**)&p_xgf, g_xgf);
    cudaGetSymbolAddress((void**)&p_xgb, g_xgb);
    cudaGetSymbolAddress((void**)&p_hf,  g_hf);
    cudaGetSymbolAddress((void**)&p_hb,  g_hb);
    cudaGetSymbolAddress((void**)&p_ghf, g_ghf);
    cudaGetSymbolAddress((void**)&p_ghb, g_ghb);
    cudaGetSymbolAddress((void**)&p_accf, g_accf);
    cudaGetSymbolAddress((void**)&p_accb, g_accb);

    // 1) node / edge input embeddings
    sgemm<128,128,16,8,8,true><<<dim3(2,128),   256>>>(NN, HH, FN, node_x, Wn, bn, p_in);
    sgemm<128,128,16,8,8,true><<<dim3(2,1024),  256>>>(EE, HH, FE, edge_x, We, be, p_ie);

    // 2) message-passing round 1 (h_e starts as i_e)
    aggregate_k<<<NN, HH>>>(p_ie, p_in, p_hn);
    sgemm<128,128,16,8,8,false><<<dim3(2,128), 256>>>(NN, HH, HH, p_hn, Wm0, bm0, p_tmp);
    edge_update_k<<<EE, HH>>>(p_ie, p_tmp, src, p_he);

    // 3) round 2
    aggregate_k<<<NN, HH>>>(p_he, p_hn, p_hn);
    sgemm<128,128,16,8,8,false><<<dim3(2,128), 256>>>(NN, HH, HH, p_hn, Wm1, bm1, p_tmp);
    edge_update_k<<<EE, HH>>>(p_ie, p_tmp, src, p_he);

    // 4) final aggregate + concat + Wlr
    build_cat_k<<<NN, HH>>>(p_he, p_hn, p_in, p_cat);
    sgemm<128,128,16,8,8,false><<<dim3(2,128), 256>>>(NN, HH, 3*HH, p_cat, Wlr, blr, p_tmp);

    // 5) GRU setup
    msg_k<<<NN, HH>>>(p_tmp, gbias, p_msg);
    init_h0_k<<<BB, HH>>>(p_tmp, p_hf, p_hb, p_accf, p_accb);
    sgemm<128,128,16,8,8,false><<<dim3(6,128), 256>>>(NN, 3*HH, HH, p_msg, Wif, bif, p_xgf);
    sgemm<128,128,16,8,8,false><<<dim3(6,128), 256>>>(NN, 3*HH, HH, p_msg, Wib, bib, p_xgb);

    // 6) GRU scan: 64 sequential steps, both directions per launch
    for (int step = 0; step < NPG; step++){
        gru_gh_k<<<dim3(12,4,2), 256>>>(p_hf, p_hb, Whf, Whb, bhf, bhb, p_ghf, p_ghb);
        gru_gate_k<<<dim3(BB,2), HH>>>(p_xgf, p_xgb, p_ghf, p_ghb,
                                       p_hf, p_hb, p_accf, p_accb, step);
    }

    // 7) readout
    readout_k<<<BB, HH>>>(p_accf, p_accb, W1, b1, W2, b2, out);
}

// round 2
// speedup vs baseline: 1.1324x; 1.1324x over previous
#include <cuda_runtime.h>
#include <cuda_bf16.h>
#include <math.h>

#define NN   16384
#define BB   256
#define NPG  64
#define DEG  8
#define EE   (NN*DEG)
#define HH   256
#define FN   133
#define FE   14
#define NPB  4    // nodes per block in fused aggregate kernels

// ---------------- scratch ----------------------------------------------------
__device__ float g_in  [NN*HH];
__device__ float g_hn  [NN*HH];
__device__ float g_tmp [NN*HH];
__device__ float g_cat [NN*3*HH];
__device__ float g_hnl [NN*HH];
__device__ float g_msg [NN*HH];
__device__ float g_xgf [NN*3*HH];
__device__ float g_xgb [NN*3*HH];
__device__ float g_hf0 [BB*HH];
__device__ float g_hf1 [BB*HH];
__device__ float g_hb0 [BB*HH];
__device__ float g_hb1 [BB*HH];
__device__ float g_accf[BB*HH];
__device__ float g_accb[BB*HH];

__device__ __forceinline__ float sigmoidf_(float x){ return 1.0f/(1.0f+expf(-x)); }

// ---------------- fp32 GEMM, 128x128x16 tiles, float4 inner LDS --------------
// C = op(A @ W + bias). blockIdx.z selects (W0,b0,C0) or (W1,b1,C1).
// M multiple of 128, N multiple of 128 (no store guards). K guarded.
template<bool RELU>
__global__ __launch_bounds__(256) void sgemm128(
    int M, int N, int K,
    const float* __restrict__ A,
    const float* __restrict__ W0, const float* __restrict__ b0, float* __restrict__ C0,
    const float* __restrict__ W1, const float* __restrict__ b1, float* __restrict__ C1)
{
    const float* W    = blockIdx.z ? W1 : W0;
    const float* bias = blockIdx.z ? b1 : b0;
    float*       C    = blockIdx.z ? C1 : C0;

    __shared__ float As[16][132];   // [k][m], row stride 132 floats (16B aligned)
    __shared__ float Ws[16][128];   // [k][n]
    const int tid = threadIdx.x;
    const int tx = tid & 15, ty = tid >> 4;
    const int row0 = blockIdx.y*128, col0 = blockIdx.x*128;

    float acc[8][8];
    #pragma unroll
    for (int i=0;i<8;i++)
        #pragma unroll
        for (int j=0;j<8;j++) acc[i][j]=0.f;

    for (int k0 = 0; k0 < K; k0 += 16){
        #pragma unroll 4
        for (int idx = tid; idx < 2048; idx += 256){
            int kk = idx & 15, m = idx >> 4;
            int gk = k0 + kk;
            As[kk][m] = (gk < K) ? A[(size_t)(row0+m)*K + gk] : 0.f;
        }
        #pragma unroll 4
        for (int idx = tid; idx < 2048; idx += 256){
            int n = idx & 127, kk = idx >> 7;
            int gk = k0 + kk;
            Ws[kk][n] = (gk < K) ? W[(size_t)gk*N + col0 + n] : 0.f;
        }
        __syncthreads();
        #pragma unroll
        for (int k = 0; k < 16; k++){
            float4 a0 = *(const float4*)&As[k][ty*8];
            float4 a1 = *(const float4*)&As[k][ty*8+4];
            float4 w0 = *(const float4*)&Ws[k][tx*8];
            float4 w1 = *(const float4*)&Ws[k][tx*8+4];
            float av[8] = {a0.x,a0.y,a0.z,a0.w,a1.x,a1.y,a1.z,a1.w};
            float bv[8] = {w0.x,w0.y,w0.z,w0.w,w1.x,w1.y,w1.z,w1.w};
            #pragma unroll
            for (int i=0;i<8;i++)
                #pragma unroll
                for (int j=0;j<8;j++)
                    acc[i][j] = fmaf(av[i], bv[j], acc[i][j]);
        }
        __syncthreads();
    }

    float bl[8];
    #pragma unroll
    for (int j=0;j<8;j++) bl[j] = bias[col0 + tx*8 + j];

    #pragma unroll
    for (int i=0;i<8;i++){
        size_t gr = (size_t)(row0 + ty*8 + i);
        float v[8];
        #pragma unroll
        for (int j=0;j<8;j++){
            v[j] = acc[i][j] + bl[j];
            if (RELU) v[j] = fmaxf(v[j], 0.f);
        }
        *(float4*)&C[gr*N + col0 + tx*8]     = make_float4(v[0],v[1],v[2],v[3]);
        *(float4*)&C[gr*N + col0 + tx*8 + 4] = make_float4(v[4],v[5],v[6],v[7]);
    }
}

// ---------- fused aggregate: on-the-fly i_e, optional tmp gather -------------
// HAS_TMP=0: h_e = i_e;  HAS_TMP=1: h_e = relu(i_e + tmp[src])
// hn_out = hn_in + segsum(h_e)*segmax(h_e)
template<bool HAS_TMP>
__global__ __launch_bounds__(256) void agg_k(
    const float* __restrict__ edge_x, const float* __restrict__ We,
    const float* __restrict__ be,     const float* __restrict__ tmp,
    const int* __restrict__ src,
    const float* __restrict__ hn_in,  float* __restrict__ hn_out)
{
    __shared__ float WeS[FE*HH];
    __shared__ float exs[NPB*DEG*FE];
    __shared__ int   srcS[NPB*DEG];
    const int tid = threadIdx.x;
    const int node0 = blockIdx.x * NPB;

    #pragma unroll
    for (int i = tid; i < FE*HH; i += 256) WeS[i] = We[i];
    for (int i = tid; i < NPB*DEG*FE; i += 256) exs[i] = edge_x[(size_t)node0*DEG*FE + i];
    if (tid < NPB*DEG) srcS[tid] = src[node0*DEG + tid];
    __syncthreads();

    const int j = tid;
    const float bej = be[j];
    #pragma unroll
    for (int nl = 0; nl < NPB; nl++){
        float tv[DEG];
        if (HAS_TMP){
            #pragma unroll
            for (int d=0; d<DEG; d++)
                tv[d] = tmp[(size_t)srcS[nl*DEG+d]*HH + j];
        }
        float s = 0.f, m = -INFINITY;
        #pragma unroll
        for (int d=0; d<DEG; d++){
            float v = bej;
            #pragma unroll
            for (int k=0; k<FE; k++)
                v = fmaf(exs[nl*DEG*FE + d*FE + k], WeS[k*HH + j], v);
            v = fmaxf(v, 0.f);
            if (HAS_TMP) v = fmaxf(v + tv[d], 0.f);
            s += v; m = fmaxf(m, v);
        }
        size_t r = (size_t)(node0+nl)*HH + j;
        hn_out[r] = hn_in[r] + s*m;
    }
}

// ---------- fused final aggregate + concat(m_final, h_n, i_n) ----------------
__global__ __launch_bounds__(256) void cat_k(
    const float* __restrict__ edge_x, const float* __restrict__ We,
    const float* __restrict__ be,     const float* __restrict__ tmp,
    const int* __restrict__ src,
    const float* __restrict__ hn,     const float* __restrict__ in_,
    float* __restrict__ cat)
{
    __shared__ float WeS[FE*HH];
    __shared__ float exs[NPB*DEG*FE];
    __shared__ int   srcS[NPB*DEG];
    const int tid = threadIdx.x;
    const int node0 = blockIdx.x * NPB;

    #pragma unroll
    for (int i = tid; i < FE*HH; i += 256) WeS[i] = We[i];
    for (int i = tid; i < NPB*DEG*FE; i += 256) exs[i] = edge_x[(size_t)node0*DEG*FE + i];
    if (tid < NPB*DEG) srcS[tid] = src[node0*DEG + tid];
    __syncthreads();

    const int j = tid;
    const float bej = be[j];
    #pragma unroll
    for (int nl = 0; nl < NPB; nl++){
        float tv[DEG];
        #pragma unroll
        for (int d=0; d<DEG; d++)
            tv[d] = tmp[(size_t)srcS[nl*DEG+d]*HH + j];
        float s = 0.f, m = -INFINITY;
        #pragma unroll
        for (int d=0; d<DEG; d++){
            float v = bej;
            #pragma unroll
            for (int k=0; k<FE; k++)
                v = fmaf(exs[nl*DEG*FE + d*FE + k], WeS[k*HH + j], v);
            v = fmaxf(v, 0.f);
            v = fmaxf(v + tv[d], 0.f);
            s += v; m = fmaxf(m, v);
        }
        int node = node0 + nl;
        size_t r = (size_t)node*3*HH;
        cat[r + j]        = s*m;
        cat[r + HH + j]   = hn[(size_t)node*HH + j];
        cat[r + 2*HH + j] = in_[(size_t)node*HH + j];
    }
}

// ---------- msg = relu(h_n + gbias) ------------------------------------------
__global__ void msg_k(const float* __restrict__ hnl, const float* __restrict__ gbias,
                      float* __restrict__ msg)
{
    int i = blockIdx.x, j = threadIdx.x;
    msg[(size_t)i*HH + j] = fmaxf(hnl[(size_t)i*HH + j] + gbias[j], 0.f);
}

// ---------- h0 = per-graph max; zero accumulators ----------------------------
__global__ void init_h0_k(const float* __restrict__ hnl,
                          float* __restrict__ hf, float* __restrict__ hb,
                          float* __restrict__ accf, float* __restrict__ accb)
{
    int b = blockIdx.x, j = threadIdx.x;
    float m = -INFINITY;
    #pragma unroll 8
    for (int t=0; t<NPG; t++)
        m = fmaxf(m, hnl[((size_t)b*NPG + t)*HH + j]);
    hf[b*HH+j] = m; hb[b*HH+j] = m;
    accf[b*HH+j] = 0.f; accb[b*HH+j] = 0.f;
}

// ---------- fused GRU step: gh GEMM + gates + h update + mean accumulate -----
// grid (8 j-tiles, 8 graph-tiles, 2 dirs), 256 threads.
// Block: 32 graphs x 32 hidden x 3 gates; K=256. Double-buffered h.
__global__ __launch_bounds__(256) void gru_step_k(
    const float* __restrict__ xgf, const float* __restrict__ xgb,
    const float* __restrict__ Whf, const float* __restrict__ Whb,
    const float* __restrict__ bhf, const float* __restrict__ bhb,
    const float* __restrict__ hf_in, const float* __restrict__ hb_in,
    float* __restrict__ hf_out, float* __restrict__ hb_out,
    float* __restrict__ accf, float* __restrict__ accb, int step)
{
    const int dir = blockIdx.z;
    const float* xg  = dir ? xgb : xgf;
    const float* Wh  = dir ? Whb : Whf;
    const float* bh  = dir ? bhb : bhf;
    const float* hin = dir ? hb_in : hf_in;
    float* hout = dir ? hb_out : hf_out;
    float* acc  = dir ? accb : accf;
    const int t = dir ? (NPG-1-step) : step;

    const int g0 = blockIdx.y*32, j0 = blockIdx.x*32;
    __shared__ float Hs[32][34];   // [k][g], even stride for float2
    __shared__ float Ws[32][98];   // [k][gate*32+jj]
    const int tid = threadIdx.x, tx = tid & 15, ty = tid >> 4;

    float a[2][6];
    #pragma unroll
    for (int i=0;i<2;i++)
        #pragma unroll
        for (int q=0;q<6;q++) a[i][q]=0.f;

    for (int k0 = 0; k0 < HH; k0 += 32){
        #pragma unroll
        for (int idx = tid; idx < 32*32; idx += 256){
            int kk = idx & 31, g = idx >> 5;
            Hs[kk][g] = hin[(size_t)(g0+g)*HH + k0 + kk];
        }
        #pragma unroll
        for (int idx = tid; idx < 32*96; idx += 256){
            int col = idx % 96, kk = idx / 96;
            int gate = col >> 5, jj = col & 31;
            Ws[kk][col] = Wh[(size_t)(k0+kk)*(3*HH) + gate*HH + j0 + jj];
        }
        __syncthreads();
        #pragma unroll
        for (int k=0;k<32;k++){
            float2 hv = *(const float2*)&Hs[k][ty*2];
            float2 b0 = *(const float2*)&Ws[k][ 0 + tx*2];
            float2 b1 = *(const float2*)&Ws[k][32 + tx*2];
            float2 b2 = *(const float2*)&Ws[k][64 + tx*2];
            a[0][0]=fmaf(hv.x,b0.x,a[0][0]); a[0][1]=fmaf(hv.x,b0.y,a[0][1]);
            a[0][2]=fmaf(hv.x,b1.x,a[0][2]); a[0][3]=fmaf(hv.x,b1.y,a[0][3]);
            a[0][4]=fmaf(hv.x,b2.x,a[0][4]); a[0][5]=fmaf(hv.x,b2.y,a[0][5]);
            a[1][0]=fmaf(hv.y,b0.x,a[1][0]); a[1][1]=fmaf(hv.y,b0.y,a[1][1]);
            a[1][2]=fmaf(hv.y,b1.x,a[1][2]); a[1][3]=fmaf(hv.y,b1.y,a[1][3]);
            a[1][4]=fmaf(hv.y,b2.x,a[1][4]); a[1][5]=fmaf(hv.y,b2.y,a[1][5]);
        }
        __syncthreads();
    }

    #pragma unroll
    for (int gm=0; gm<2; gm++){
        const int g = g0 + ty*2 + gm;
        const float* x = xg + ((size_t)g*NPG + t)*(3*HH);
        #pragma unroll
        for (int jj=0; jj<2; jj++){
            const int j = j0 + tx*2 + jj;
            float r = sigmoidf_(x[j]        + a[gm][0+jj] + bh[j]);
            float z = sigmoidf_(x[HH + j]   + a[gm][2+jj] + bh[HH + j]);
            float n = tanhf    (x[2*HH + j] + r*(a[gm][4+jj] + bh[2*HH + j]));
            float hold = hin[(size_t)g*HH + j];
            float hn = (1.0f - z)*n + z*hold;
            hout[(size_t)g*HH + j] = hn;
            acc[(size_t)g*HH + j] += hn;
        }
    }
}

// ---------- readout: out = relu(g@W1+b1)@W2 + b2 -----------------------------
__global__ void readout_k(const float* __restrict__ accf, const float* __restrict__ accb,
                          const float* __restrict__ W1, const float* __restrict__ b1,
                          const float* __restrict__ W2, const float* __restrict__ b2,
                          float* __restrict__ out)
{
    int b = blockIdx.x, j = threadIdx.x;
    __shared__ float gsh[2*HH];
    __shared__ float red[HH];
    gsh[j]      = accf[b*HH + j] * (1.0f/NPG);
    gsh[HH + j] = accb[b*HH + j] * (1.0f/NPG);
    __syncthreads();
    float y = b1[j];
    #pragma unroll 8
    for (int k=0; k<2*HH; k++)
        y = fmaf(gsh[k], W1[k*HH + j], y);
    y = fmaxf(y, 0.f);
    red[j] = y * W2[j];
    __syncthreads();
    for (int s=128; s>0; s>>=1){
        if (j < s) red[j] += red[j+s];
        __syncthreads();
    }
    if (j == 0) out[b] = red[0] + b2[0];
}

// =============================================================================
extern "C" void kernel_launch(void* const* d_in, const int* in_sizes, int n_in,
                              void* d_out, int out_size)
{
    const float* node_x = (const float*)d_in[0];
    const float* edge_x = (const float*)d_in[1];
    const int*   src    = (const int*)  d_in[2];
    const float* Wn  = (const float*)d_in[4];  const float* bn  = (const float*)d_in[5];
    const float* We  = (const float*)d_in[6];  const float* be  = (const float*)d_in[7];
    const float* Wm0 = (const float*)d_in[8];  const float* bm0 = (const float*)d_in[9];
    const float* Wm1 = (const float*)d_in[10]; const float* bm1 = (const float*)d_in[11];
    const float* Wlr = (const float*)d_in[12]; const float* blr = (const float*)d_in[13];
    const float* gbias = (const float*)d_in[14];
    const float* Wif = (const float*)d_in[15]; const float* Whf = (const float*)d_in[16];
    const float* bif = (const float*)d_in[17]; const float* bhf = (const float*)d_in[18];
    const float* Wib = (const float*)d_in[19]; const float* Whb = (const float*)d_in[20];
    const float* bib = (const float*)d_in[21]; const float* bhb = (const float*)d_in[22];
    const float* W1  = (const float*)d_in[23]; const float* b1  = (const float*)d_in[24];
    const float* W2  = (const float*)d_in[25]; const float* b2  = (const float*)d_in[26];
    float* out = (float*)d_out;

    float *p_in,*p_hn,*p_tmp,*p_cat,*p_hnl,*p_msg,*p_xgf,*p_xgb;
    float *p_hf0,*p_hf1,*p_hb0,*p_hb1,*p_accf,*p_accb;
    cudaGetSymbolAddress((void**)&p_in,  g_in);
    cudaGetSymbolAddress((void**)&p_hn,  g_hn);
    cudaGetSymbolAddress((void**)&p_tmp, g_tmp);
    cudaGetSymbolAddress((void**)&p_cat, g_cat);
    cudaGetSymbolAddress((void**)&p_hnl, g_hnl);
    cudaGetSymbolAddress((void**)&p_msg, g_msg);
    cudaGetSymbolAddress((void**)&p_xgf, g_xgf);
    cudaGetSymbolAddress((void**)&p_xgb, g_xgb);
    cudaGetSymbolAddress((void**)&p_hf0, g_hf0);
    cudaGetSymbolAddress((void**)&p_hf1, g_hf1);
    cudaGetSymbolAddress((void**)&p_hb0, g_hb0);
    cudaGetSymbolAddress((void**)&p_hb1, g_hb1);
    cudaGetSymbolAddress((void**)&p_accf, g_accf);
    cudaGetSymbolAddress((void**)&p_accb, g_accb);

    // 1) node embedding: i_n = relu(node_x @ Wn + bn)
    sgemm128<true><<<dim3(2,128,1), 256>>>(NN, HH, FN, node_x, Wn, bn, p_in, Wn, bn, p_in);

    // 2) round 1: h_n = i_n + segsum(i_e)*segmax(i_e)   (i_e computed on the fly)
    agg_k<false><<<NN/NPB, 256>>>(edge_x, We, be, nullptr, src, p_in, p_hn);
    sgemm128<false><<<dim3(2,128,1), 256>>>(NN, HH, HH, p_hn, Wm0, bm0, p_tmp, Wm0, bm0, p_tmp);

    // 3) round 2: h_e = relu(i_e + tmp[src]); h_n += segsum*segmax
    agg_k<true><<<NN/NPB, 256>>>(edge_x, We, be, p_tmp, src, p_hn, p_hn);
    sgemm128<false><<<dim3(2,128,1), 256>>>(NN, HH, HH, p_hn, Wm1, bm1, p_tmp, Wm1, bm1, p_tmp);

    // 4) final aggregate + concat + Wlr
    cat_k<<<NN/NPB, 256>>>(edge_x, We, be, p_tmp, src, p_hn, p_in, p_cat);
    sgemm128<false><<<dim3(2,128,1), 256>>>(NN, HH, 3*HH, p_cat, Wlr, blr, p_hnl, Wlr, blr, p_hnl);

    // 5) GRU setup
    msg_k<<<NN, HH>>>(p_hnl, gbias, p_msg);
    init_h0_k<<<BB, HH>>>(p_hnl, p_hf0, p_hb0, p_accf, p_accb);
    sgemm128<false><<<dim3(6,128,2), 256>>>(NN, 3*HH, HH, p_msg,
                                            Wif, bif, p_xgf, Wib, bib, p_xgb);

    // 6) GRU scan: 64 fused steps, double-buffered h
    for (int step = 0; step < NPG; step++){
        float* hf_in  = (step & 1) ? p_hf1 : p_hf0;
        float* hf_out = (step & 1) ? p_hf0 : p_hf1;
        float* hb_in  = (step & 1) ? p_hb1 : p_hb0;
        float* hb_out = (step & 1) ? p_hb0 : p_hb1;
        gru_step_k<<<dim3(8,8,2), 256>>>(p_xgf, p_xgb, Whf, Whb, bhf, bhb,
                                         hf_in, hb_in, hf_out, hb_out,
                                         p_accf, p_accb, step);
    }

    // 7) readout
    readout_k<<<BB, HH>>>(p_accf, p_accb, W1, b1, W2, b2, out);
}